// round 10
// baseline (speedup 1.0000x reference)
#include <cuda_runtime.h>
#include <math_constants.h>
#include <stdint.h>

#define D_MODEL 768
#define NHEAD   12
#define DH      64
#define BATCH   4
#define SEQ     2048
#define M_ROWS  (BATCH*SEQ)            /* 8192 */
#define HSZ     (BATCH*NHEAD*SEQ*DH)   /* 6291456 per matrix */
#define WSZ     (D_MODEL*D_MODEL)      /* 589824 */

// Scratch (allocation-free rule: __device__ globals)
__device__ float g_QKV[3*HSZ];
__device__ float g_A[M_ROWS*D_MODEL];
__device__ float g_xt[M_ROWS*D_MODEL];
__device__ float g_Wt[4*WSZ];

// ---------------------------------------------------------------------------
// helpers
// ---------------------------------------------------------------------------
__device__ __forceinline__ unsigned f2tf(float f) {
    unsigned u;
    asm("cvt.rna.tf32.f32 %0, %1;" : "=r"(u) : "f"(f));
    return u;
}

__device__ __forceinline__ void mma_tf32(float* c, const unsigned* a,
                                         unsigned b0, unsigned b1) {
    asm volatile(
        "mma.sync.aligned.m16n8k8.row.col.f32.tf32.tf32.f32 "
        "{%0,%1,%2,%3}, {%4,%5,%6,%7}, {%8,%9}, {%0,%1,%2,%3};"
        : "+f"(c[0]), "+f"(c[1]), "+f"(c[2]), "+f"(c[3])
        : "r"(a[0]), "r"(a[1]), "r"(a[2]), "r"(a[3]), "r"(b0), "r"(b1));
}

__device__ __forceinline__ void cp16(void* smem, const void* gmem) {
    uint32_t sa = (uint32_t)__cvta_generic_to_shared(smem);
    asm volatile("cp.async.cg.shared.global [%0], [%1], 16;" :: "r"(sa), "l"(gmem));
}
__device__ __forceinline__ void cp_commit() {
    asm volatile("cp.async.commit_group;" ::: "memory");
}
template <int N>
__device__ __forceinline__ void cp_wait() {
    asm volatile("cp.async.wait_group %0;" :: "n"(N) : "memory");
}

// ---------------------------------------------------------------------------
// tf32 (RNA) pre-conversion kernels
// ---------------------------------------------------------------------------
__global__ __launch_bounds__(256) void cvt_tf32(const float* __restrict__ in,
                                                float* __restrict__ out, int n4)
{
    int i = blockIdx.x*256 + threadIdx.x;
    if (i < n4) {
        float4 v = ((const float4*)in)[i];
        v.x = __uint_as_float(f2tf(v.x));
        v.y = __uint_as_float(f2tf(v.y));
        v.z = __uint_as_float(f2tf(v.z));
        v.w = __uint_as_float(f2tf(v.w));
        ((float4*)out)[i] = v;
    }
}

__global__ __launch_bounds__(256) void cvt_w4(
    const float* __restrict__ w0, const float* __restrict__ w1,
    const float* __restrict__ w2, const float* __restrict__ w3,
    float* __restrict__ out)
{
    const int z = blockIdx.z;
    const float* in = (z == 0) ? w0 : (z == 1) ? w1 : (z == 2) ? w2 : w3;
    int i = blockIdx.x*256 + threadIdx.x;
    if (i < WSZ/4) {
        float4 v = ((const float4*)in)[i];
        v.x = __uint_as_float(f2tf(v.x));
        v.y = __uint_as_float(f2tf(v.y));
        v.z = __uint_as_float(f2tf(v.z));
        v.w = __uint_as_float(f2tf(v.w));
        ((float4*)(out + (size_t)z*WSZ))[i] = v;
    }
}

// ---------------------------------------------------------------------------
// TF32 GEMM: C = A @ W^T + bias.  A,W already tf32-rounded.
// 256 thr (8 warps), block tile 128x128, warp tile 64x32 (wm 2 x wn 4).
// acc = 64 regs/thread -> ~110 regs -> 2 blocks/SM = 16 warps/SM.
// 2-stage cp.async double buffer, one barrier per k-block.
// ---------------------------------------------------------------------------
#define NKB   (D_MODEL/16)   /* 48 */
#define AST   20
__global__ __launch_bounds__(256, 2) void gemm_tc(
    const float* __restrict__ A,
    const float* __restrict__ W0, const float* __restrict__ W1,
    const float* __restrict__ W2,
    const float* __restrict__ b0v, const float* __restrict__ b1v,
    const float* __restrict__ b2v,
    float* __restrict__ C, int mode)
{
    __shared__ __align__(16) float As[2][128][AST];
    __shared__ __align__(16) float Ws[2][128][AST];

    const int mat = blockIdx.z;
    const float* W    = (mat == 0) ? W0 : (mat == 1 ? W1 : W2);
    const float* bias = (mat == 0) ? b0v : (mat == 1 ? b1v : b2v);
    float* Cout = (mode == 1) ? (C + (size_t)mat * HSZ) : C;

    const int t    = threadIdx.x;
    const int warp = t >> 5;
    const int lane = t & 31;
    const int lq   = lane >> 2;
    const int lj   = lane & 3;
    const int wm   = warp & 1;       // m half (64 rows)
    const int wn   = warp >> 1;      // n quarter (32 cols)
    const int bm   = blockIdx.y * 128;
    const int bn   = blockIdx.x * 128;

    // staging: 256 thr, each 2 cp16 per matrix (row t>>1, cols (t&1)*8..+7)
    const int lrow = t >> 1;
    const int lc   = (t & 1) * 8;
    const float* Ap = A + (size_t)(bm + lrow) * D_MODEL + lc;
    const float* Wp = W + (size_t)(bn + lrow) * D_MODEL + lc;

    float acc[4][4][4];
    #pragma unroll
    for (int mb = 0; mb < 4; mb++)
        #pragma unroll
        for (int nb = 0; nb < 4; nb++)
            #pragma unroll
            for (int c = 0; c < 4; c++) acc[mb][nb][c] = 0.f;

    cp16(&As[0][lrow][lc], Ap);
    cp16(&As[0][lrow][lc+4], Ap + 4);
    cp16(&Ws[0][lrow][lc], Wp);
    cp16(&Ws[0][lrow][lc+4], Wp + 4);
    cp_commit();

    for (int kb = 0; kb < NKB; kb++) {
        cp_wait<0>();
        __syncthreads();

        if (kb + 1 < NKB) {
            const int s1 = (kb+1) & 1;
            const int k0 = (kb+1)*16;
            cp16(&As[s1][lrow][lc], Ap + k0);
            cp16(&As[s1][lrow][lc+4], Ap + k0 + 4);
            cp16(&Ws[s1][lrow][lc], Wp + k0);
            cp16(&Ws[s1][lrow][lc+4], Wp + k0 + 4);
            cp_commit();
        }

        const int s = kb & 1;
        #pragma unroll
        for (int kk = 0; kk < 16; kk += 8) {
            unsigned af[4][4];
            #pragma unroll
            for (int mb = 0; mb < 4; mb++) {
                const int m0 = wm*64 + mb*16;
                af[mb][0] = __float_as_uint(As[s][m0+lq  ][kk+lj  ]);
                af[mb][1] = __float_as_uint(As[s][m0+lq+8][kk+lj  ]);
                af[mb][2] = __float_as_uint(As[s][m0+lq  ][kk+lj+4]);
                af[mb][3] = __float_as_uint(As[s][m0+lq+8][kk+lj+4]);
            }
            #pragma unroll
            for (int nb = 0; nb < 4; nb++) {
                const int nc = wn*32 + nb*8 + lq;
                unsigned bb0 = __float_as_uint(Ws[s][nc][kk+lj  ]);
                unsigned bb1 = __float_as_uint(Ws[s][nc][kk+lj+4]);
                #pragma unroll
                for (int mb = 0; mb < 4; mb++)
                    mma_tf32(acc[mb][nb], af[mb], bb0, bb1);
            }
        }
    }

    // epilogue
    #pragma unroll
    for (int mb = 0; mb < 4; mb++) {
        const int gi = bm + wm*64 + mb*16 + lq;
        const int bb = gi >> 11, ss = gi & 2047;
        #pragma unroll
        for (int nb = 0; nb < 4; nb++) {
            const int gjl = bn + wn*32 + nb*8 + 2*lj;
            const float bv0 = bias[gjl], bv1 = bias[gjl+1];
            float2 r0, r1;
            r0.x = acc[mb][nb][0] + bv0; r0.y = acc[mb][nb][1] + bv1;
            r1.x = acc[mb][nb][2] + bv0; r1.y = acc[mb][nb][3] + bv1;
            if (mode == 0) {
                *(float2*)(Cout + (size_t)gi * D_MODEL + gjl)     = r0;
                *(float2*)(Cout + (size_t)(gi+8) * D_MODEL + gjl) = r1;
            } else {
                r0.x = __uint_as_float(f2tf(r0.x));
                r0.y = __uint_as_float(f2tf(r0.y));
                r1.x = __uint_as_float(f2tf(r1.x));
                r1.y = __uint_as_float(f2tf(r1.y));
                const int h = gjl >> 6, d = gjl & 63;
                float* p = Cout + (((size_t)bb*NHEAD + h)*SEQ)*DH + d;
                *(float2*)(p + (size_t)ss*DH)     = r0;
                *(float2*)(p + (size_t)(ss+8)*DH) = r1;
            }
        }
    }
}

// ---------------------------------------------------------------------------
// Flash attention, TF32 mma, no-max softmax. 128 thr (4 warps) = 64 queries;
// warp tile 16 rows, ~128 regs -> 4 blocks/SM = 16 warps in 4 INDEPENDENT
// blocks (block-level interleave hides per-tile serial exp/barrier sections).
// cp.async double-buffered K/V, one barrier per tile.
// ---------------------------------------------------------------------------
#define KT 32
#define NT (SEQ/KT)
#define KST 68
#define VST 72
#define PST 36
#define SM_KS   0
#define SM_VS   (SM_KS + 2*KT*KST*4)              /* 17408 */
#define SM_PS   (SM_VS + 2*KT*VST*4)              /* +18432 = 35840 */
#define SM_MS   (SM_PS + 64*PST*4)                /* +9216  = 45056 */
#define SM_ATTN (SM_MS + SEQ*4)                   /* +8192  = 53248 */

__global__ __launch_bounds__(128, 4) void attn_tc(
    const float* __restrict__ Q, const float* __restrict__ K,
    const float* __restrict__ V, const int* __restrict__ mask,
    const float* __restrict__ temp, float* __restrict__ O)
{
    extern __shared__ __align__(16) char sm[];
    float (*Ks)[KT][KST] = (float(*)[KT][KST])(sm + SM_KS);
    float (*Vs)[KT][VST] = (float(*)[KT][VST])(sm + SM_VS);
    float (*Ps)[PST]     = (float(*)[PST])    (sm + SM_PS);
    int*  mS             = (int*)             (sm + SM_MS);

    const int bh = blockIdx.y;
    const int b  = bh / NHEAD, h = bh % NHEAD;
    const int q0 = blockIdx.x * 64;
    const float scale = temp[h] * 0.125f;
    const size_t base = (size_t)bh * SEQ * DH;

    const int t    = threadIdx.x;
    const int warp = t >> 5;
    const int lane = t & 31;
    const int lq   = lane >> 2;
    const int lj   = lane & 3;

    // staging map: 128 threads cover 32 keys x 64 floats (4 cp16 each matrix)
    const int skey = t >> 2;          // 0..31
    const int sd0  = (t & 3) * 16;    // 0,16,32,48

    // prologue: stage tile 0 + preload mask row
    {
        const float* kp = K + base + (size_t)skey*DH + sd0;
        const float* vp = V + base + (size_t)skey*DH + sd0;
        #pragma unroll
        for (int c = 0; c < 4; c++) cp16(&Ks[0][skey][sd0 + c*4], kp + c*4);
        #pragma unroll
        for (int c = 0; c < 4; c++) cp16(&Vs[0][skey][sd0 + c*4], vp + c*4);
        cp_commit();
        #pragma unroll
        for (int i = 0; i < SEQ/128; i++) mS[i*128 + t] = mask[b*SEQ + i*128 + t];
    }

    // Q in A fragments (16 rows per warp), pre-scaled, tf32-rounded
    unsigned qa[8][4];
    {
        const float* qp0 = Q + base + (size_t)(q0 + warp*16 + lq) * DH;
        const float* qp1 = qp0 + 8 * DH;
        #pragma unroll
        for (int ks = 0; ks < 8; ks++) {
            const int c0 = ks*8 + lj;
            qa[ks][0] = f2tf(qp0[c0]   * scale);
            qa[ks][1] = f2tf(qp1[c0]   * scale);
            qa[ks][2] = f2tf(qp0[c0+4] * scale);
            qa[ks][3] = f2tf(qp1[c0+4] * scale);
        }
    }

    float ls0 = 0.f, ls1 = 0.f;
    float o[8][4];
    #pragma unroll
    for (int nb = 0; nb < 8; nb++)
        #pragma unroll
        for (int c = 0; c < 4; c++) o[nb][c] = 0.f;

    const int prow = warp*16 + lq;

    for (int kt = 0; kt < NT; kt++) {
        cp_wait<0>();
        __syncthreads();   // tile kt visible; iter kt-1 reads of other buf done

        if (kt + 1 < NT) {   // prefetch AFTER barrier
            const int s1 = (kt+1) & 1;
            const int k1 = (kt+1) * KT;
            const float* kp = K + base + (size_t)(k1 + skey)*DH + sd0;
            const float* vp = V + base + (size_t)(k1 + skey)*DH + sd0;
            #pragma unroll
            for (int c = 0; c < 4; c++) cp16(&Ks[s1][skey][sd0 + c*4], kp + c*4);
            #pragma unroll
            for (int c = 0; c < 4; c++) cp16(&Vs[s1][skey][sd0 + c*4], vp + c*4);
            cp_commit();
        }

        const int s  = kt & 1;
        const int k0 = kt * KT;

        // ---- S = (scale*Q) K^T : 16x32 per warp ----
        float sc[4][4];
        #pragma unroll
        for (int nb = 0; nb < 4; nb++)
            #pragma unroll
            for (int c = 0; c < 4; c++) sc[nb][c] = 0.f;

        #pragma unroll
        for (int nb = 0; nb < 4; nb++) {
            const int ncol = nb*8 + lq;
            #pragma unroll
            for (int ks = 0; ks < 8; ks++) {
                unsigned b0 = __float_as_uint(Ks[s][ncol][ks*8 + lj    ]);
                unsigned b1 = __float_as_uint(Ks[s][ncol][ks*8 + lj + 4]);
                mma_tf32(sc[nb], qa[ks], b0, b1);
            }
        }

        // ---- p = mask ? exp(s) : 0 ; partial sums; store P ----
        #pragma unroll
        for (int nb = 0; nb < 4; nb++) {
            const int col0 = nb*8 + 2*lj;
            const int km0 = mS[k0 + col0], km1 = mS[k0 + col0 + 1];
            float p00 = km0 ? __expf(sc[nb][0]) : 0.f;
            float p01 = km1 ? __expf(sc[nb][1]) : 0.f;
            float p10 = km0 ? __expf(sc[nb][2]) : 0.f;
            float p11 = km1 ? __expf(sc[nb][3]) : 0.f;
            ls0 += p00 + p01;
            ls1 += p10 + p11;
            float2 w0, w1;
            w0.x = __uint_as_float(f2tf(p00));
            w0.y = __uint_as_float(f2tf(p01));
            w1.x = __uint_as_float(f2tf(p10));
            w1.y = __uint_as_float(f2tf(p11));
            *(float2*)&Ps[prow    ][col0] = w0;
            *(float2*)&Ps[prow + 8][col0] = w1;
        }

        __syncwarp();   // P visible within warp (reads own 16 rows only)

        // ---- O += P V ----
        #pragma unroll
        for (int ks = 0; ks < 4; ks++) {
            unsigned pa[4];
            const int pc = ks*8 + lj;
            pa[0] = __float_as_uint(Ps[prow    ][pc]);
            pa[1] = __float_as_uint(Ps[prow + 8][pc]);
            pa[2] = __float_as_uint(Ps[prow    ][pc+4]);
            pa[3] = __float_as_uint(Ps[prow + 8][pc+4]);
            #pragma unroll
            for (int nb = 0; nb < 8; nb++) {
                const int ncol = nb*8 + lq;
                unsigned b0 = __float_as_uint(Vs[s][ks*8 + lj    ][ncol]);
                unsigned b1 = __float_as_uint(Vs[s][ks*8 + lj + 4][ncol]);
                mma_tf32(o[nb], pa, b0, b1);
            }
        }
    }

    // ---- epilogue: reduce row sums, normalize, write tf32-rounded ----
    ls0 += __shfl_xor_sync(0xffffffffu, ls0, 1);
    ls0 += __shfl_xor_sync(0xffffffffu, ls0, 2);
    ls1 += __shfl_xor_sync(0xffffffffu, ls1, 1);
    ls1 += __shfl_xor_sync(0xffffffffu, ls1, 2);
    const float inv0 = 1.0f / ls0;
    const float inv1 = 1.0f / ls1;
    const int qr = q0 + warp*16 + lq;
    float* op0 = O + ((size_t)b*SEQ + qr    )*D_MODEL + h*DH;
    float* op1 = O + ((size_t)b*SEQ + qr + 8)*D_MODEL + h*DH;
    #pragma unroll
    for (int nb = 0; nb < 8; nb++) {
        const int col = nb*8 + 2*lj;
        float2 r0c, r1c;
        r0c.x = __uint_as_float(f2tf(o[nb][0]*inv0));
        r0c.y = __uint_as_float(f2tf(o[nb][1]*inv0));
        r1c.x = __uint_as_float(f2tf(o[nb][2]*inv1));
        r1c.y = __uint_as_float(f2tf(o[nb][3]*inv1));
        *(float2*)(op0 + col) = r0c;
        *(float2*)(op1 + col) = r1c;
    }
}

// ---------------------------------------------------------------------------
extern "C" void kernel_launch(void* const* d_in, const int* in_sizes, int n_in,
                              void* d_out, int out_size)
{
    (void)in_sizes; (void)n_in; (void)out_size;
    const float* x    = (const float*)d_in[0];
    const int*   mask = (const int*)  d_in[1];
    const float* Wq   = (const float*)d_in[2];
    const float* bq   = (const float*)d_in[3];
    const float* Wk   = (const float*)d_in[4];
    const float* bk   = (const float*)d_in[5];
    const float* Wv   = (const float*)d_in[6];
    const float* bv   = (const float*)d_in[7];
    const float* Wo   = (const float*)d_in[8];
    const float* bo   = (const float*)d_in[9];
    const float* temp = (const float*)d_in[10];

    float *QKVb, *Ab, *xt, *Wt;
    cudaGetSymbolAddress((void**)&QKVb, g_QKV);
    cudaGetSymbolAddress((void**)&Ab,   g_A);
    cudaGetSymbolAddress((void**)&xt,   g_xt);
    cudaGetSymbolAddress((void**)&Wt,   g_Wt);

    static int attr_set = 0;
    if (!attr_set) {
        cudaFuncSetAttribute(attn_tc,
            cudaFuncAttributeMaxDynamicSharedMemorySize, SM_ATTN);
        attr_set = 1;
    }

    cvt_tf32<<<(M_ROWS*D_MODEL/4 + 255)/256, 256>>>(x, xt, M_ROWS*D_MODEL/4);
    cvt_w4<<<dim3((WSZ/4 + 255)/256, 1, 4), 256>>>(Wq, Wk, Wv, Wo, Wt);

    gemm_tc<<<dim3(D_MODEL/128, M_ROWS/128, 3), 256>>>(
        xt, Wt, Wt + WSZ, Wt + 2*WSZ, bq, bk, bv, QKVb, 1);

    attn_tc<<<dim3(SEQ/64, BATCH*NHEAD), 128, SM_ATTN>>>(
        QKVb, QKVb + HSZ, QKVb + 2*(size_t)HSZ, mask, temp, Ab);

    gemm_tc<<<dim3(D_MODEL/128, M_ROWS/128, 1), 256>>>(
        Ab, Wt + 3*WSZ, Wt + 3*WSZ, Wt + 3*WSZ, bo, bo, bo, (float*)d_out, 0);
}

// round 11
// speedup vs baseline: 1.1158x; 1.1158x over previous
#include <cuda_runtime.h>
#include <math_constants.h>
#include <stdint.h>

#define D_MODEL 768
#define NHEAD   12
#define DH      64
#define BATCH   4
#define SEQ     2048
#define M_ROWS  (BATCH*SEQ)            /* 8192 */
#define HSZ     (BATCH*NHEAD*SEQ*DH)   /* 6291456 per matrix */
#define WSZ     (D_MODEL*D_MODEL)      /* 589824 */

// Scratch (allocation-free rule: __device__ globals)
__device__ float g_QKV[3*HSZ];
__device__ float g_A[M_ROWS*D_MODEL];
__device__ float g_xt[M_ROWS*D_MODEL];
__device__ float g_Wt[4*WSZ];

// ---------------------------------------------------------------------------
// helpers
// ---------------------------------------------------------------------------
__device__ __forceinline__ unsigned f2tf(float f) {
    unsigned u;
    asm("cvt.rna.tf32.f32 %0, %1;" : "=r"(u) : "f"(f));
    return u;
}

__device__ __forceinline__ void mma_tf32(float* c, const unsigned* a,
                                         unsigned b0, unsigned b1) {
    asm volatile(
        "mma.sync.aligned.m16n8k8.row.col.f32.tf32.tf32.f32 "
        "{%0,%1,%2,%3}, {%4,%5,%6,%7}, {%8,%9}, {%0,%1,%2,%3};"
        : "+f"(c[0]), "+f"(c[1]), "+f"(c[2]), "+f"(c[3])
        : "r"(a[0]), "r"(a[1]), "r"(a[2]), "r"(a[3]), "r"(b0), "r"(b1));
}

__device__ __forceinline__ void cp16(void* smem, const void* gmem) {
    uint32_t sa = (uint32_t)__cvta_generic_to_shared(smem);
    asm volatile("cp.async.cg.shared.global [%0], [%1], 16;" :: "r"(sa), "l"(gmem));
}
__device__ __forceinline__ void cp_commit() {
    asm volatile("cp.async.commit_group;" ::: "memory");
}
template <int N>
__device__ __forceinline__ void cp_wait() {
    asm volatile("cp.async.wait_group %0;" :: "n"(N) : "memory");
}

// ---------------------------------------------------------------------------
// tf32 (RNA) pre-conversion kernels
// ---------------------------------------------------------------------------
__global__ __launch_bounds__(256) void cvt_tf32(const float* __restrict__ in,
                                                float* __restrict__ out, int n4)
{
    int i = blockIdx.x*256 + threadIdx.x;
    if (i < n4) {
        float4 v = ((const float4*)in)[i];
        v.x = __uint_as_float(f2tf(v.x));
        v.y = __uint_as_float(f2tf(v.y));
        v.z = __uint_as_float(f2tf(v.z));
        v.w = __uint_as_float(f2tf(v.w));
        ((float4*)out)[i] = v;
    }
}

__global__ __launch_bounds__(256) void cvt_w4(
    const float* __restrict__ w0, const float* __restrict__ w1,
    const float* __restrict__ w2, const float* __restrict__ w3,
    float* __restrict__ out)
{
    const int z = blockIdx.z;
    const float* in = (z == 0) ? w0 : (z == 1) ? w1 : (z == 2) ? w2 : w3;
    int i = blockIdx.x*256 + threadIdx.x;
    if (i < WSZ/4) {
        float4 v = ((const float4*)in)[i];
        v.x = __uint_as_float(f2tf(v.x));
        v.y = __uint_as_float(f2tf(v.y));
        v.z = __uint_as_float(f2tf(v.z));
        v.w = __uint_as_float(f2tf(v.w));
        ((float4*)(out + (size_t)z*WSZ))[i] = v;
    }
}

// ---------------------------------------------------------------------------
// TF32 GEMM (R10 config — measured good): 256 thr (8 warps), block tile
// 128x128, warp tile 64x32, 2 blocks/SM = 16 warps/SM. cp.async 2-stage.
// ---------------------------------------------------------------------------
#define NKB   (D_MODEL/16)   /* 48 */
#define AST   20
__global__ __launch_bounds__(256, 2) void gemm_tc(
    const float* __restrict__ A,
    const float* __restrict__ W0, const float* __restrict__ W1,
    const float* __restrict__ W2,
    const float* __restrict__ b0v, const float* __restrict__ b1v,
    const float* __restrict__ b2v,
    float* __restrict__ C, int mode)
{
    __shared__ __align__(16) float As[2][128][AST];
    __shared__ __align__(16) float Ws[2][128][AST];

    const int mat = blockIdx.z;
    const float* W    = (mat == 0) ? W0 : (mat == 1 ? W1 : W2);
    const float* bias = (mat == 0) ? b0v : (mat == 1 ? b1v : b2v);
    float* Cout = (mode == 1) ? (C + (size_t)mat * HSZ) : C;

    const int t    = threadIdx.x;
    const int warp = t >> 5;
    const int lane = t & 31;
    const int lq   = lane >> 2;
    const int lj   = lane & 3;
    const int wm   = warp & 1;       // m half (64 rows)
    const int wn   = warp >> 1;      // n quarter (32 cols)
    const int bm   = blockIdx.y * 128;
    const int bn   = blockIdx.x * 128;

    const int lrow = t >> 1;
    const int lc   = (t & 1) * 8;
    const float* Ap = A + (size_t)(bm + lrow) * D_MODEL + lc;
    const float* Wp = W + (size_t)(bn + lrow) * D_MODEL + lc;

    float acc[4][4][4];
    #pragma unroll
    for (int mb = 0; mb < 4; mb++)
        #pragma unroll
        for (int nb = 0; nb < 4; nb++)
            #pragma unroll
            for (int c = 0; c < 4; c++) acc[mb][nb][c] = 0.f;

    cp16(&As[0][lrow][lc], Ap);
    cp16(&As[0][lrow][lc+4], Ap + 4);
    cp16(&Ws[0][lrow][lc], Wp);
    cp16(&Ws[0][lrow][lc+4], Wp + 4);
    cp_commit();

    for (int kb = 0; kb < NKB; kb++) {
        cp_wait<0>();
        __syncthreads();

        if (kb + 1 < NKB) {
            const int s1 = (kb+1) & 1;
            const int k0 = (kb+1)*16;
            cp16(&As[s1][lrow][lc], Ap + k0);
            cp16(&As[s1][lrow][lc+4], Ap + k0 + 4);
            cp16(&Ws[s1][lrow][lc], Wp + k0);
            cp16(&Ws[s1][lrow][lc+4], Wp + k0 + 4);
            cp_commit();
        }

        const int s = kb & 1;
        #pragma unroll
        for (int kk = 0; kk < 16; kk += 8) {
            unsigned af[4][4];
            #pragma unroll
            for (int mb = 0; mb < 4; mb++) {
                const int m0 = wm*64 + mb*16;
                af[mb][0] = __float_as_uint(As[s][m0+lq  ][kk+lj  ]);
                af[mb][1] = __float_as_uint(As[s][m0+lq+8][kk+lj  ]);
                af[mb][2] = __float_as_uint(As[s][m0+lq  ][kk+lj+4]);
                af[mb][3] = __float_as_uint(As[s][m0+lq+8][kk+lj+4]);
            }
            #pragma unroll
            for (int nb = 0; nb < 4; nb++) {
                const int nc = wn*32 + nb*8 + lq;
                unsigned bb0 = __float_as_uint(Ws[s][nc][kk+lj  ]);
                unsigned bb1 = __float_as_uint(Ws[s][nc][kk+lj+4]);
                #pragma unroll
                for (int mb = 0; mb < 4; mb++)
                    mma_tf32(acc[mb][nb], af[mb], bb0, bb1);
            }
        }
    }

    #pragma unroll
    for (int mb = 0; mb < 4; mb++) {
        const int gi = bm + wm*64 + mb*16 + lq;
        const int bb = gi >> 11, ss = gi & 2047;
        #pragma unroll
        for (int nb = 0; nb < 4; nb++) {
            const int gjl = bn + wn*32 + nb*8 + 2*lj;
            const float bv0 = bias[gjl], bv1 = bias[gjl+1];
            float2 r0, r1;
            r0.x = acc[mb][nb][0] + bv0; r0.y = acc[mb][nb][1] + bv1;
            r1.x = acc[mb][nb][2] + bv0; r1.y = acc[mb][nb][3] + bv1;
            if (mode == 0) {
                *(float2*)(Cout + (size_t)gi * D_MODEL + gjl)     = r0;
                *(float2*)(Cout + (size_t)(gi+8) * D_MODEL + gjl) = r1;
            } else {
                r0.x = __uint_as_float(f2tf(r0.x));
                r0.y = __uint_as_float(f2tf(r0.y));
                r1.x = __uint_as_float(f2tf(r1.x));
                r1.y = __uint_as_float(f2tf(r1.y));
                const int h = gjl >> 6, d = gjl & 63;
                float* p = Cout + (((size_t)bb*NHEAD + h)*SEQ)*DH + d;
                *(float2*)(p + (size_t)ss*DH)     = r0;
                *(float2*)(p + (size_t)(ss+8)*DH) = r1;
            }
        }
    }
}

// ---------------------------------------------------------------------------
// Flash attention (R9 config — measured 480us): 256 thr (8 warps) = 128
// queries; warp tile 16 rows, 128 regs, 2 blocks/SM = 16 warps/SM.
// cp.async double-buffered K/V, one barrier per tile, no-max softmax.
// ---------------------------------------------------------------------------
#define KT 32
#define NT (SEQ/KT)
#define KST 68
#define VST 72
#define PST 36
#define SM_KS   0
#define SM_VS   (SM_KS + 2*KT*KST*4)              /* 17408 */
#define SM_PS   (SM_VS + 2*KT*VST*4)              /* +18432 = 35840 */
#define SM_MS   (SM_PS + 128*PST*4)               /* +18432 = 54272 */
#define SM_ATTN (SM_MS + SEQ*4)                   /* +8192  = 62464 */

__global__ __launch_bounds__(256, 2) void attn_tc(
    const float* __restrict__ Q, const float* __restrict__ K,
    const float* __restrict__ V, const int* __restrict__ mask,
    const float* __restrict__ temp, float* __restrict__ O)
{
    extern __shared__ __align__(16) char sm[];
    float (*Ks)[KT][KST] = (float(*)[KT][KST])(sm + SM_KS);
    float (*Vs)[KT][VST] = (float(*)[KT][VST])(sm + SM_VS);
    float (*Ps)[PST]     = (float(*)[PST])    (sm + SM_PS);
    int*  mS             = (int*)             (sm + SM_MS);

    const int bh = blockIdx.y;
    const int b  = bh / NHEAD, h = bh % NHEAD;
    const int q0 = blockIdx.x * 128;
    const float scale = temp[h] * 0.125f;
    const size_t base = (size_t)bh * SEQ * DH;

    const int t    = threadIdx.x;
    const int warp = t >> 5;
    const int lane = t & 31;
    const int lq   = lane >> 2;
    const int lj   = lane & 3;

    // staging map: 256 threads cover 32 keys x 64 floats (2 cp16 each)
    const int skey = t >> 3;          // 0..31
    const int sd0  = (t & 7) * 8;     // 0,8,...,56

    // prologue: stage tile 0 + preload mask row
    {
        const float* kp = K + base + (size_t)skey*DH + sd0;
        const float* vp = V + base + (size_t)skey*DH + sd0;
        cp16(&Ks[0][skey][sd0    ], kp);
        cp16(&Ks[0][skey][sd0 + 4], kp + 4);
        cp16(&Vs[0][skey][sd0    ], vp);
        cp16(&Vs[0][skey][sd0 + 4], vp + 4);
        cp_commit();
        #pragma unroll
        for (int i = 0; i < SEQ/256; i++) mS[i*256 + t] = mask[b*SEQ + i*256 + t];
    }

    // Q in A fragments (16 rows per warp), pre-scaled, tf32-rounded
    unsigned qa[8][4];
    {
        const float* qp0 = Q + base + (size_t)(q0 + warp*16 + lq) * DH;
        const float* qp1 = qp0 + 8 * DH;
        #pragma unroll
        for (int ks = 0; ks < 8; ks++) {
            const int c0 = ks*8 + lj;
            qa[ks][0] = f2tf(qp0[c0]   * scale);
            qa[ks][1] = f2tf(qp1[c0]   * scale);
            qa[ks][2] = f2tf(qp0[c0+4] * scale);
            qa[ks][3] = f2tf(qp1[c0+4] * scale);
        }
    }

    float ls0 = 0.f, ls1 = 0.f;
    float o[8][4];
    #pragma unroll
    for (int nb = 0; nb < 8; nb++)
        #pragma unroll
        for (int c = 0; c < 4; c++) o[nb][c] = 0.f;

    const int prow = warp*16 + lq;

    for (int kt = 0; kt < NT; kt++) {
        cp_wait<0>();
        __syncthreads();   // tile kt visible; iter kt-1 reads of other buf done

        if (kt + 1 < NT) {   // prefetch AFTER barrier
            const int s1 = (kt+1) & 1;
            const int k1 = (kt+1) * KT;
            const float* kp = K + base + (size_t)(k1 + skey)*DH + sd0;
            const float* vp = V + base + (size_t)(k1 + skey)*DH + sd0;
            cp16(&Ks[s1][skey][sd0    ], kp);
            cp16(&Ks[s1][skey][sd0 + 4], kp + 4);
            cp16(&Vs[s1][skey][sd0    ], vp);
            cp16(&Vs[s1][skey][sd0 + 4], vp + 4);
            cp_commit();
        }

        const int s  = kt & 1;
        const int k0 = kt * KT;

        // ---- S = (scale*Q) K^T : 16x32 per warp ----
        float sc[4][4];
        #pragma unroll
        for (int nb = 0; nb < 4; nb++)
            #pragma unroll
            for (int c = 0; c < 4; c++) sc[nb][c] = 0.f;

        #pragma unroll
        for (int nb = 0; nb < 4; nb++) {
            const int ncol = nb*8 + lq;
            #pragma unroll
            for (int ks = 0; ks < 8; ks++) {
                unsigned b0 = __float_as_uint(Ks[s][ncol][ks*8 + lj    ]);
                unsigned b1 = __float_as_uint(Ks[s][ncol][ks*8 + lj + 4]);
                mma_tf32(sc[nb], qa[ks], b0, b1);
            }
        }

        // ---- p = mask ? exp(s) : 0 ; partial sums; store P ----
        #pragma unroll
        for (int nb = 0; nb < 4; nb++) {
            const int col0 = nb*8 + 2*lj;
            const int km0 = mS[k0 + col0], km1 = mS[k0 + col0 + 1];
            float p00 = km0 ? __expf(sc[nb][0]) : 0.f;
            float p01 = km1 ? __expf(sc[nb][1]) : 0.f;
            float p10 = km0 ? __expf(sc[nb][2]) : 0.f;
            float p11 = km1 ? __expf(sc[nb][3]) : 0.f;
            ls0 += p00 + p01;
            ls1 += p10 + p11;
            float2 w0, w1;
            w0.x = __uint_as_float(f2tf(p00));
            w0.y = __uint_as_float(f2tf(p01));
            w1.x = __uint_as_float(f2tf(p10));
            w1.y = __uint_as_float(f2tf(p11));
            *(float2*)&Ps[prow    ][col0] = w0;
            *(float2*)&Ps[prow + 8][col0] = w1;
        }

        __syncwarp();   // P visible within warp (reads own 16 rows only)

        // ---- O += P V ----
        #pragma unroll
        for (int ks = 0; ks < 4; ks++) {
            unsigned pa[4];
            const int pc = ks*8 + lj;
            pa[0] = __float_as_uint(Ps[prow    ][pc]);
            pa[1] = __float_as_uint(Ps[prow + 8][pc]);
            pa[2] = __float_as_uint(Ps[prow    ][pc+4]);
            pa[3] = __float_as_uint(Ps[prow + 8][pc+4]);
            #pragma unroll
            for (int nb = 0; nb < 8; nb++) {
                const int ncol = nb*8 + lq;
                unsigned b0 = __float_as_uint(Vs[s][ks*8 + lj    ][ncol]);
                unsigned b1 = __float_as_uint(Vs[s][ks*8 + lj + 4][ncol]);
                mma_tf32(o[nb], pa, b0, b1);
            }
        }
    }

    // ---- epilogue: reduce row sums, normalize, write tf32-rounded ----
    ls0 += __shfl_xor_sync(0xffffffffu, ls0, 1);
    ls0 += __shfl_xor_sync(0xffffffffu, ls0, 2);
    ls1 += __shfl_xor_sync(0xffffffffu, ls1, 1);
    ls1 += __shfl_xor_sync(0xffffffffu, ls1, 2);
    const float inv0 = 1.0f / ls0;
    const float inv1 = 1.0f / ls1;
    const int qr = q0 + warp*16 + lq;
    float* op0 = O + ((size_t)b*SEQ + qr    )*D_MODEL + h*DH;
    float* op1 = O + ((size_t)b*SEQ + qr + 8)*D_MODEL + h*DH;
    #pragma unroll
    for (int nb = 0; nb < 8; nb++) {
        const int col = nb*8 + 2*lj;
        float2 r0c, r1c;
        r0c.x = __uint_as_float(f2tf(o[nb][0]*inv0));
        r0c.y = __uint_as_float(f2tf(o[nb][1]*inv0));
        r1c.x = __uint_as_float(f2tf(o[nb][2]*inv1));
        r1c.y = __uint_as_float(f2tf(o[nb][3]*inv1));
        *(float2*)(op0 + col) = r0c;
        *(float2*)(op1 + col) = r1c;
    }
}

// ---------------------------------------------------------------------------
extern "C" void kernel_launch(void* const* d_in, const int* in_sizes, int n_in,
                              void* d_out, int out_size)
{
    (void)in_sizes; (void)n_in; (void)out_size;
    const float* x    = (const float*)d_in[0];
    const int*   mask = (const int*)  d_in[1];
    const float* Wq   = (const float*)d_in[2];
    const float* bq   = (const float*)d_in[3];
    const float* Wk   = (const float*)d_in[4];
    const float* bk   = (const float*)d_in[5];
    const float* Wv   = (const float*)d_in[6];
    const float* bv   = (const float*)d_in[7];
    const float* Wo   = (const float*)d_in[8];
    const float* bo   = (const float*)d_in[9];
    const float* temp = (const float*)d_in[10];

    float *QKVb, *Ab, *xt, *Wt;
    cudaGetSymbolAddress((void**)&QKVb, g_QKV);
    cudaGetSymbolAddress((void**)&Ab,   g_A);
    cudaGetSymbolAddress((void**)&xt,   g_xt);
    cudaGetSymbolAddress((void**)&Wt,   g_Wt);

    static int attr_set = 0;
    if (!attr_set) {
        cudaFuncSetAttribute(attn_tc,
            cudaFuncAttributeMaxDynamicSharedMemorySize, SM_ATTN);
        attr_set = 1;
    }

    cvt_tf32<<<(M_ROWS*D_MODEL/4 + 255)/256, 256>>>(x, xt, M_ROWS*D_MODEL/4);
    cvt_w4<<<dim3((WSZ/4 + 255)/256, 1, 4), 256>>>(Wq, Wk, Wv, Wo, Wt);

    gemm_tc<<<dim3(D_MODEL/128, M_ROWS/128, 3), 256>>>(
        xt, Wt, Wt + WSZ, Wt + 2*WSZ, bq, bk, bv, QKVb, 1);

    attn_tc<<<dim3(SEQ/128, BATCH*NHEAD), 256, SM_ATTN>>>(
        QKVb, QKVb + HSZ, QKVb + 2*(size_t)HSZ, mask, temp, Ab);

    gemm_tc<<<dim3(D_MODEL/128, M_ROWS/128, 1), 256>>>(
        Ab, Wt + 3*WSZ, Wt + 3*WSZ, Wt + 3*WSZ, bo, bo, bo, (float*)d_out, 0);
}

// round 12
// speedup vs baseline: 1.1635x; 1.0427x over previous
#include <cuda_runtime.h>
#include <math_constants.h>
#include <stdint.h>

#define D_MODEL 768
#define NHEAD   12
#define DH      64
#define BATCH   4
#define SEQ     2048
#define M_ROWS  (BATCH*SEQ)            /* 8192 */
#define HSZ     (BATCH*NHEAD*SEQ*DH)   /* 6291456 per matrix */
#define WSZ     (D_MODEL*D_MODEL)      /* 589824 */

// Scratch (allocation-free rule: __device__ globals)
__device__ float g_QKV[3*HSZ];
__device__ float g_A[M_ROWS*D_MODEL];
__device__ float g_xt[M_ROWS*D_MODEL];
__device__ float g_Wt[4*WSZ];

// ---------------------------------------------------------------------------
// helpers
// ---------------------------------------------------------------------------
__device__ __forceinline__ unsigned f2tf(float f) {
    unsigned u;
    asm("cvt.rna.tf32.f32 %0, %1;" : "=r"(u) : "f"(f));
    return u;
}

__device__ __forceinline__ void mma_tf32(float* c, const unsigned* a,
                                         unsigned b0, unsigned b1) {
    asm volatile(
        "mma.sync.aligned.m16n8k8.row.col.f32.tf32.tf32.f32 "
        "{%0,%1,%2,%3}, {%4,%5,%6,%7}, {%8,%9}, {%0,%1,%2,%3};"
        : "+f"(c[0]), "+f"(c[1]), "+f"(c[2]), "+f"(c[3])
        : "r"(a[0]), "r"(a[1]), "r"(a[2]), "r"(a[3]), "r"(b0), "r"(b1));
}

__device__ __forceinline__ void cp16(void* smem, const void* gmem) {
    uint32_t sa = (uint32_t)__cvta_generic_to_shared(smem);
    asm volatile("cp.async.cg.shared.global [%0], [%1], 16;" :: "r"(sa), "l"(gmem));
}
__device__ __forceinline__ void cp_commit() {
    asm volatile("cp.async.commit_group;" ::: "memory");
}
template <int N>
__device__ __forceinline__ void cp_wait() {
    asm volatile("cp.async.wait_group %0;" :: "n"(N) : "memory");
}

// ---------------------------------------------------------------------------
// tf32 (RNA) pre-conversion kernels
// ---------------------------------------------------------------------------
__global__ __launch_bounds__(256) void cvt_tf32(const float* __restrict__ in,
                                                float* __restrict__ out, int n4)
{
    int i = blockIdx.x*256 + threadIdx.x;
    if (i < n4) {
        float4 v = ((const float4*)in)[i];
        v.x = __uint_as_float(f2tf(v.x));
        v.y = __uint_as_float(f2tf(v.y));
        v.z = __uint_as_float(f2tf(v.z));
        v.w = __uint_as_float(f2tf(v.w));
        ((float4*)out)[i] = v;
    }
}

__global__ __launch_bounds__(256) void cvt_w4(
    const float* __restrict__ w0, const float* __restrict__ w1,
    const float* __restrict__ w2, const float* __restrict__ w3,
    float* __restrict__ out)
{
    const int z = blockIdx.z;
    const float* in = (z == 0) ? w0 : (z == 1) ? w1 : (z == 2) ? w2 : w3;
    int i = blockIdx.x*256 + threadIdx.x;
    if (i < WSZ/4) {
        float4 v = ((const float4*)in)[i];
        v.x = __uint_as_float(f2tf(v.x));
        v.y = __uint_as_float(f2tf(v.y));
        v.z = __uint_as_float(f2tf(v.z));
        v.w = __uint_as_float(f2tf(v.w));
        ((float4*)(out + (size_t)z*WSZ))[i] = v;
    }
}

// ---------------------------------------------------------------------------
// TF32 GEMM: 256 thr (8 warps), block tile 128x128, warp tile 64x32,
// 2 blocks/SM. cp.async 2-stage. mode 1: mat 0/1 (Q/K) head-split [B,H,S,64];
// mat 2 (V) TRANSPOSED head-split [B,H,64,S] (attention wants V d-major).
// ---------------------------------------------------------------------------
#define NKB   (D_MODEL/16)   /* 48 */
#define AST   20
__global__ __launch_bounds__(256, 2) void gemm_tc(
    const float* __restrict__ A,
    const float* __restrict__ W0, const float* __restrict__ W1,
    const float* __restrict__ W2,
    const float* __restrict__ b0v, const float* __restrict__ b1v,
    const float* __restrict__ b2v,
    float* __restrict__ C, int mode)
{
    __shared__ __align__(16) float As[2][128][AST];
    __shared__ __align__(16) float Ws[2][128][AST];

    const int mat = blockIdx.z;
    const float* W    = (mat == 0) ? W0 : (mat == 1 ? W1 : W2);
    const float* bias = (mat == 0) ? b0v : (mat == 1 ? b1v : b2v);
    float* Cout = (mode == 1) ? (C + (size_t)mat * HSZ) : C;

    const int t    = threadIdx.x;
    const int warp = t >> 5;
    const int lane = t & 31;
    const int lq   = lane >> 2;
    const int lj   = lane & 3;
    const int wm   = warp & 1;
    const int wn   = warp >> 1;
    const int bm   = blockIdx.y * 128;
    const int bn   = blockIdx.x * 128;

    const int lrow = t >> 1;
    const int lc   = (t & 1) * 8;
    const float* Ap = A + (size_t)(bm + lrow) * D_MODEL + lc;
    const float* Wp = W + (size_t)(bn + lrow) * D_MODEL + lc;

    float acc[4][4][4];
    #pragma unroll
    for (int mb = 0; mb < 4; mb++)
        #pragma unroll
        for (int nb = 0; nb < 4; nb++)
            #pragma unroll
            for (int c = 0; c < 4; c++) acc[mb][nb][c] = 0.f;

    cp16(&As[0][lrow][lc], Ap);
    cp16(&As[0][lrow][lc+4], Ap + 4);
    cp16(&Ws[0][lrow][lc], Wp);
    cp16(&Ws[0][lrow][lc+4], Wp + 4);
    cp_commit();

    for (int kb = 0; kb < NKB; kb++) {
        cp_wait<0>();
        __syncthreads();

        if (kb + 1 < NKB) {
            const int s1 = (kb+1) & 1;
            const int k0 = (kb+1)*16;
            cp16(&As[s1][lrow][lc], Ap + k0);
            cp16(&As[s1][lrow][lc+4], Ap + k0 + 4);
            cp16(&Ws[s1][lrow][lc], Wp + k0);
            cp16(&Ws[s1][lrow][lc+4], Wp + k0 + 4);
            cp_commit();
        }

        const int s = kb & 1;
        #pragma unroll
        for (int kk = 0; kk < 16; kk += 8) {
            unsigned af[4][4];
            #pragma unroll
            for (int mb = 0; mb < 4; mb++) {
                const int m0 = wm*64 + mb*16;
                af[mb][0] = __float_as_uint(As[s][m0+lq  ][kk+lj  ]);
                af[mb][1] = __float_as_uint(As[s][m0+lq+8][kk+lj  ]);
                af[mb][2] = __float_as_uint(As[s][m0+lq  ][kk+lj+4]);
                af[mb][3] = __float_as_uint(As[s][m0+lq+8][kk+lj+4]);
            }
            #pragma unroll
            for (int nb = 0; nb < 4; nb++) {
                const int nc = wn*32 + nb*8 + lq;
                unsigned bb0 = __float_as_uint(Ws[s][nc][kk+lj  ]);
                unsigned bb1 = __float_as_uint(Ws[s][nc][kk+lj+4]);
                #pragma unroll
                for (int mb = 0; mb < 4; mb++)
                    mma_tf32(acc[mb][nb], af[mb], bb0, bb1);
            }
        }
    }

    #pragma unroll
    for (int mb = 0; mb < 4; mb++) {
        const int gi = bm + wm*64 + mb*16 + lq;
        const int bb = gi >> 11, ss = gi & 2047;
        #pragma unroll
        for (int nb = 0; nb < 4; nb++) {
            const int gjl = bn + wn*32 + nb*8 + 2*lj;
            const float bv0 = bias[gjl], bv1 = bias[gjl+1];
            float2 r0, r1;
            r0.x = acc[mb][nb][0] + bv0; r0.y = acc[mb][nb][1] + bv1;
            r1.x = acc[mb][nb][2] + bv0; r1.y = acc[mb][nb][3] + bv1;
            if (mode == 0) {
                *(float2*)(Cout + (size_t)gi * D_MODEL + gjl)     = r0;
                *(float2*)(Cout + (size_t)(gi+8) * D_MODEL + gjl) = r1;
            } else {
                r0.x = __uint_as_float(f2tf(r0.x));
                r0.y = __uint_as_float(f2tf(r0.y));
                r1.x = __uint_as_float(f2tf(r1.x));
                r1.y = __uint_as_float(f2tf(r1.y));
                const int h = gjl >> 6, d = gjl & 63;
                if (mat == 2) {
                    // V transposed: [B,H,64,S]
                    float* p = Cout + (((size_t)bb*NHEAD + h)*DH + d)*SEQ + ss;
                    p[0]          = r0.x;
                    p[SEQ]        = r0.y;
                    p[8]          = r1.x;
                    p[SEQ + 8]    = r1.y;
                } else {
                    float* p = Cout + (((size_t)bb*NHEAD + h)*SEQ)*DH + d;
                    *(float2*)(p + (size_t)ss*DH)     = r0;
                    *(float2*)(p + (size_t)(ss+8)*DH) = r1;
                }
            }
        }
    }
}

// ---------------------------------------------------------------------------
// Flash attention, TF32 mma, no-max softmax, 256 thr = 128 queries, warp
// tile 16 rows, 2 blocks/SM. LDS.64 fragment loads via contraction-slot
// reindex (slot lj <-> 2lj, lj+4 <-> 2lj+1): K pairs adjacent in Ks[key][d];
// V transposed in gmem -> Vt[d][key] pairs adjacent; Ps pairs adjacent.
// Strides = 8 (mod 32) -> conflict-free paired loads.
// ---------------------------------------------------------------------------
#define KT 32
#define NT (SEQ/KT)
#define KST 72
#define VTS 40
#define PST 40
#define SM_KS   0
#define SM_VT   (SM_KS + 2*KT*KST*4)              /* 18432 */
#define SM_PS   (SM_VT + 2*DH*VTS*4)              /* +20480 = 38912 */
#define SM_MS   (SM_PS + 128*PST*4)               /* +20480 = 59392 */
#define SM_ATTN (SM_MS + SEQ*4)                   /* +8192  = 67584 */

__global__ __launch_bounds__(256, 2) void attn_tc(
    const float* __restrict__ Q, const float* __restrict__ K,
    const float* __restrict__ Vt_g, const int* __restrict__ mask,
    const float* __restrict__ temp, float* __restrict__ O)
{
    extern __shared__ __align__(16) char sm[];
    float (*Ks)[KT][KST] = (float(*)[KT][KST])(sm + SM_KS);
    float (*Vt)[DH][VTS] = (float(*)[DH][VTS])(sm + SM_VT);
    float (*Ps)[PST]     = (float(*)[PST])    (sm + SM_PS);
    int*  mS             = (int*)             (sm + SM_MS);

    const int bh = blockIdx.y;
    const int b  = bh / NHEAD, h = bh % NHEAD;
    const int q0 = blockIdx.x * 128;
    const float scale = temp[h] * 0.125f;
    const size_t base  = (size_t)bh * SEQ * DH;   // Q,K layout [S,64]
    const size_t baseV = (size_t)bh * DH * SEQ;   // V layout [64,S]

    const int t    = threadIdx.x;
    const int warp = t >> 5;
    const int lane = t & 31;
    const int lq   = lane >> 2;
    const int lj   = lane & 3;

    // K staging map: 32 keys x 64 d; thread covers (skey, sd0..sd0+7)
    const int skey = t >> 3;          // 0..31
    const int sd0  = (t & 7) * 8;     // 0,8,...,56
    // V staging map: 64 d-rows x 32 keys; thread covers (vd, vk0..vk0+7)
    const int vd   = t >> 2;          // 0..63
    const int vk0  = (t & 3) * 8;     // 0,8,16,24

    // prologue: stage tile 0 + preload mask row
    {
        const float* kp = K    + base  + (size_t)skey*DH + sd0;
        const float* vp = Vt_g + baseV + (size_t)vd*SEQ  + vk0;
        cp16(&Ks[0][skey][sd0    ], kp);
        cp16(&Ks[0][skey][sd0 + 4], kp + 4);
        cp16(&Vt[0][vd][vk0    ], vp);
        cp16(&Vt[0][vd][vk0 + 4], vp + 4);
        cp_commit();
        #pragma unroll
        for (int i = 0; i < SEQ/256; i++) mS[i*256 + t] = mask[b*SEQ + i*256 + t];
    }

    // Q in A fragments, slot-reindexed (slot lj holds d=2lj, slot lj+4 holds
    // d=2lj+1), pre-scaled, tf32-rounded
    unsigned qa[8][4];
    {
        const float* qp0 = Q + base + (size_t)(q0 + warp*16 + lq) * DH;
        const float* qp1 = qp0 + 8 * DH;
        #pragma unroll
        for (int ks = 0; ks < 8; ks++) {
            const int c0 = ks*8 + 2*lj;
            qa[ks][0] = f2tf(qp0[c0]   * scale);
            qa[ks][1] = f2tf(qp1[c0]   * scale);
            qa[ks][2] = f2tf(qp0[c0+1] * scale);
            qa[ks][3] = f2tf(qp1[c0+1] * scale);
        }
    }

    float ls0 = 0.f, ls1 = 0.f;
    float o[8][4];
    #pragma unroll
    for (int nb = 0; nb < 8; nb++)
        #pragma unroll
        for (int c = 0; c < 4; c++) o[nb][c] = 0.f;

    const int prow = warp*16 + lq;

    for (int kt = 0; kt < NT; kt++) {
        cp_wait<0>();
        __syncthreads();

        if (kt + 1 < NT) {
            const int s1 = (kt+1) & 1;
            const int k1 = (kt+1) * KT;
            const float* kp = K    + base  + (size_t)(k1 + skey)*DH + sd0;
            const float* vp = Vt_g + baseV + (size_t)vd*SEQ + k1 + vk0;
            cp16(&Ks[s1][skey][sd0    ], kp);
            cp16(&Ks[s1][skey][sd0 + 4], kp + 4);
            cp16(&Vt[s1][vd][vk0    ], vp);
            cp16(&Vt[s1][vd][vk0 + 4], vp + 4);
            cp_commit();
        }

        const int s  = kt & 1;
        const int k0 = kt * KT;

        // ---- S = (scale*Q) K^T : 16x32 per warp; paired LDS.64 B-frags ----
        float sc[4][4];
        #pragma unroll
        for (int nb = 0; nb < 4; nb++)
            #pragma unroll
            for (int c = 0; c < 4; c++) sc[nb][c] = 0.f;

        #pragma unroll
        for (int nb = 0; nb < 4; nb++) {
            const int ncol = nb*8 + lq;
            #pragma unroll
            for (int ks = 0; ks < 8; ks++) {
                float2 kv = *(const float2*)&Ks[s][ncol][ks*8 + 2*lj];
                mma_tf32(sc[nb], qa[ks],
                         __float_as_uint(kv.x), __float_as_uint(kv.y));
            }
        }

        // ---- p = mask ? exp(s) : 0 ; partial sums; store P ----
        #pragma unroll
        for (int nb = 0; nb < 4; nb++) {
            const int col0 = nb*8 + 2*lj;
            const int km0 = mS[k0 + col0], km1 = mS[k0 + col0 + 1];
            float p00 = km0 ? __expf(sc[nb][0]) : 0.f;
            float p01 = km1 ? __expf(sc[nb][1]) : 0.f;
            float p10 = km0 ? __expf(sc[nb][2]) : 0.f;
            float p11 = km1 ? __expf(sc[nb][3]) : 0.f;
            ls0 += p00 + p01;
            ls1 += p10 + p11;
            float2 w0, w1;
            w0.x = __uint_as_float(f2tf(p00));
            w0.y = __uint_as_float(f2tf(p01));
            w1.x = __uint_as_float(f2tf(p10));
            w1.y = __uint_as_float(f2tf(p11));
            *(float2*)&Ps[prow    ][col0] = w0;
            *(float2*)&Ps[prow + 8][col0] = w1;
        }

        __syncwarp();   // P visible within warp (reads own 16 rows only)

        // ---- O += P V : paired LDS.64 for P (A) and Vt (B) frags ----
        #pragma unroll
        for (int ks = 0; ks < 4; ks++) {
            unsigned pa[4];
            const int pc = ks*8 + 2*lj;
            float2 pv0 = *(const float2*)&Ps[prow    ][pc];
            float2 pv1 = *(const float2*)&Ps[prow + 8][pc];
            pa[0] = __float_as_uint(pv0.x);
            pa[1] = __float_as_uint(pv1.x);
            pa[2] = __float_as_uint(pv0.y);
            pa[3] = __float_as_uint(pv1.y);
            #pragma unroll
            for (int nb = 0; nb < 8; nb++) {
                const int ncol = nb*8 + lq;
                float2 vv = *(const float2*)&Vt[s][ncol][ks*8 + 2*lj];
                mma_tf32(o[nb], pa,
                         __float_as_uint(vv.x), __float_as_uint(vv.y));
            }
        }
    }

    // ---- epilogue: reduce row sums, normalize, write tf32-rounded ----
    ls0 += __shfl_xor_sync(0xffffffffu, ls0, 1);
    ls0 += __shfl_xor_sync(0xffffffffu, ls0, 2);
    ls1 += __shfl_xor_sync(0xffffffffu, ls1, 1);
    ls1 += __shfl_xor_sync(0xffffffffu, ls1, 2);
    const float inv0 = 1.0f / ls0;
    const float inv1 = 1.0f / ls1;
    const int qr = q0 + warp*16 + lq;
    float* op0 = O + ((size_t)b*SEQ + qr    )*D_MODEL + h*DH;
    float* op1 = O + ((size_t)b*SEQ + qr + 8)*D_MODEL + h*DH;
    #pragma unroll
    for (int nb = 0; nb < 8; nb++) {
        const int col = nb*8 + 2*lj;
        float2 r0c, r1c;
        r0c.x = __uint_as_float(f2tf(o[nb][0]*inv0));
        r0c.y = __uint_as_float(f2tf(o[nb][1]*inv0));
        r1c.x = __uint_as_float(f2tf(o[nb][2]*inv1));
        r1c.y = __uint_as_float(f2tf(o[nb][3]*inv1));
        *(float2*)(op0 + col) = r0c;
        *(float2*)(op1 + col) = r1c;
    }
}

// ---------------------------------------------------------------------------
extern "C" void kernel_launch(void* const* d_in, const int* in_sizes, int n_in,
                              void* d_out, int out_size)
{
    (void)in_sizes; (void)n_in; (void)out_size;
    const float* x    = (const float*)d_in[0];
    const int*   mask = (const int*)  d_in[1];
    const float* Wq   = (const float*)d_in[2];
    const float* bq   = (const float*)d_in[3];
    const float* Wk   = (const float*)d_in[4];
    const float* bk   = (const float*)d_in[5];
    const float* Wv   = (const float*)d_in[6];
    const float* bv   = (const float*)d_in[7];
    const float* Wo   = (const float*)d_in[8];
    const float* bo   = (const float*)d_in[9];
    const float* temp = (const float*)d_in[10];

    float *QKVb, *Ab, *xt, *Wt;
    cudaGetSymbolAddress((void**)&QKVb, g_QKV);
    cudaGetSymbolAddress((void**)&Ab,   g_A);
    cudaGetSymbolAddress((void**)&xt,   g_xt);
    cudaGetSymbolAddress((void**)&Wt,   g_Wt);

    static int attr_set = 0;
    if (!attr_set) {
        cudaFuncSetAttribute(attn_tc,
            cudaFuncAttributeMaxDynamicSharedMemorySize, SM_ATTN);
        attr_set = 1;
    }

    cvt_tf32<<<(M_ROWS*D_MODEL/4 + 255)/256, 256>>>(x, xt, M_ROWS*D_MODEL/4);
    cvt_w4<<<dim3((WSZ/4 + 255)/256, 1, 4), 256>>>(Wq, Wk, Wv, Wo, Wt);

    gemm_tc<<<dim3(D_MODEL/128, M_ROWS/128, 3), 256>>>(
        xt, Wt, Wt + WSZ, Wt + 2*WSZ, bq, bk, bv, QKVb, 1);

    attn_tc<<<dim3(SEQ/128, BATCH*NHEAD), 256, SM_ATTN>>>(
        QKVb, QKVb + HSZ, QKVb + 2*(size_t)HSZ, mask, temp, Ab);

    gemm_tc<<<dim3(D_MODEL/128, M_ROWS/128, 1), 256>>>(
        Ab, Wt + 3*WSZ, Wt + 3*WSZ, Wt + 3*WSZ, bo, bo, bo, (float*)d_out, 0);
}

// round 13
// speedup vs baseline: 1.2791x; 1.0994x over previous
#include <cuda_runtime.h>
#include <math_constants.h>
#include <stdint.h>

#define D_MODEL 768
#define NHEAD   12
#define DH      64
#define BATCH   4
#define SEQ     2048
#define M_ROWS  (BATCH*SEQ)            /* 8192 */
#define HSZ     (BATCH*NHEAD*SEQ*DH)   /* 6291456 per matrix */
#define WSZ     (D_MODEL*D_MODEL)      /* 589824 */

// Scratch (allocation-free rule: __device__ globals)
__device__ float g_QKV[3*HSZ];
__device__ float g_A[M_ROWS*D_MODEL];
__device__ float g_xt[M_ROWS*D_MODEL];
__device__ float g_Wt[4*WSZ];

// ---------------------------------------------------------------------------
// helpers
// ---------------------------------------------------------------------------
__device__ __forceinline__ unsigned f2tf(float f) {
    unsigned u;
    asm("cvt.rna.tf32.f32 %0, %1;" : "=r"(u) : "f"(f));
    return u;
}

__device__ __forceinline__ float ex2(float x) {
    float r;
    asm("ex2.approx.f32 %0, %1;" : "=f"(r) : "f"(x));
    return r;
}

__device__ __forceinline__ void mma_tf32(float* c, const unsigned* a,
                                         unsigned b0, unsigned b1) {
    asm volatile(
        "mma.sync.aligned.m16n8k8.row.col.f32.tf32.tf32.f32 "
        "{%0,%1,%2,%3}, {%4,%5,%6,%7}, {%8,%9}, {%0,%1,%2,%3};"
        : "+f"(c[0]), "+f"(c[1]), "+f"(c[2]), "+f"(c[3])
        : "r"(a[0]), "r"(a[1]), "r"(a[2]), "r"(a[3]), "r"(b0), "r"(b1));
}

__device__ __forceinline__ void cp16(void* smem, const void* gmem) {
    uint32_t sa = (uint32_t)__cvta_generic_to_shared(smem);
    asm volatile("cp.async.cg.shared.global [%0], [%1], 16;" :: "r"(sa), "l"(gmem));
}
__device__ __forceinline__ void cp_commit() {
    asm volatile("cp.async.commit_group;" ::: "memory");
}
template <int N>
__device__ __forceinline__ void cp_wait() {
    asm volatile("cp.async.wait_group %0;" :: "n"(N) : "memory");
}

// ---------------------------------------------------------------------------
// tf32 (RNA) pre-conversion kernels
// ---------------------------------------------------------------------------
__global__ __launch_bounds__(256) void cvt_tf32(const float* __restrict__ in,
                                                float* __restrict__ out, int n4)
{
    int i = blockIdx.x*256 + threadIdx.x;
    if (i < n4) {
        float4 v = ((const float4*)in)[i];
        v.x = __uint_as_float(f2tf(v.x));
        v.y = __uint_as_float(f2tf(v.y));
        v.z = __uint_as_float(f2tf(v.z));
        v.w = __uint_as_float(f2tf(v.w));
        ((float4*)out)[i] = v;
    }
}

__global__ __launch_bounds__(256) void cvt_w4(
    const float* __restrict__ w0, const float* __restrict__ w1,
    const float* __restrict__ w2, const float* __restrict__ w3,
    float* __restrict__ out)
{
    const int z = blockIdx.z;
    const float* in = (z == 0) ? w0 : (z == 1) ? w1 : (z == 2) ? w2 : w3;
    int i = blockIdx.x*256 + threadIdx.x;
    if (i < WSZ/4) {
        float4 v = ((const float4*)in)[i];
        v.x = __uint_as_float(f2tf(v.x));
        v.y = __uint_as_float(f2tf(v.y));
        v.z = __uint_as_float(f2tf(v.z));
        v.w = __uint_as_float(f2tf(v.w));
        ((float4*)(out + (size_t)z*WSZ))[i] = v;
    }
}

// ---------------------------------------------------------------------------
// TF32 GEMM: 256 thr (8 warps), block tile 128x128, warp tile 64x32,
// 2 blocks/SM. cp.async 2-stage. mode 1: mat 0/1 (Q/K) head-split [B,H,S,64];
// mat 2 (V) TRANSPOSED head-split [B,H,64,S].
// ---------------------------------------------------------------------------
#define NKB   (D_MODEL/16)   /* 48 */
#define AST   20
__global__ __launch_bounds__(256, 2) void gemm_tc(
    const float* __restrict__ A,
    const float* __restrict__ W0, const float* __restrict__ W1,
    const float* __restrict__ W2,
    const float* __restrict__ b0v, const float* __restrict__ b1v,
    const float* __restrict__ b2v,
    float* __restrict__ C, int mode)
{
    __shared__ __align__(16) float As[2][128][AST];
    __shared__ __align__(16) float Ws[2][128][AST];

    const int mat = blockIdx.z;
    const float* W    = (mat == 0) ? W0 : (mat == 1 ? W1 : W2);
    const float* bias = (mat == 0) ? b0v : (mat == 1 ? b1v : b2v);
    float* Cout = (mode == 1) ? (C + (size_t)mat * HSZ) : C;

    const int t    = threadIdx.x;
    const int warp = t >> 5;
    const int lane = t & 31;
    const int lq   = lane >> 2;
    const int lj   = lane & 3;
    const int wm   = warp & 1;
    const int wn   = warp >> 1;
    const int bm   = blockIdx.y * 128;
    const int bn   = blockIdx.x * 128;

    const int lrow = t >> 1;
    const int lc   = (t & 1) * 8;
    const float* Ap = A + (size_t)(bm + lrow) * D_MODEL + lc;
    const float* Wp = W + (size_t)(bn + lrow) * D_MODEL + lc;

    float acc[4][4][4];
    #pragma unroll
    for (int mb = 0; mb < 4; mb++)
        #pragma unroll
        for (int nb = 0; nb < 4; nb++)
            #pragma unroll
            for (int c = 0; c < 4; c++) acc[mb][nb][c] = 0.f;

    cp16(&As[0][lrow][lc], Ap);
    cp16(&As[0][lrow][lc+4], Ap + 4);
    cp16(&Ws[0][lrow][lc], Wp);
    cp16(&Ws[0][lrow][lc+4], Wp + 4);
    cp_commit();

    for (int kb = 0; kb < NKB; kb++) {
        cp_wait<0>();
        __syncthreads();

        if (kb + 1 < NKB) {
            const int s1 = (kb+1) & 1;
            const int k0 = (kb+1)*16;
            cp16(&As[s1][lrow][lc], Ap + k0);
            cp16(&As[s1][lrow][lc+4], Ap + k0 + 4);
            cp16(&Ws[s1][lrow][lc], Wp + k0);
            cp16(&Ws[s1][lrow][lc+4], Wp + k0 + 4);
            cp_commit();
        }

        const int s = kb & 1;
        #pragma unroll
        for (int kk = 0; kk < 16; kk += 8) {
            unsigned af[4][4];
            #pragma unroll
            for (int mb = 0; mb < 4; mb++) {
                const int m0 = wm*64 + mb*16;
                af[mb][0] = __float_as_uint(As[s][m0+lq  ][kk+lj  ]);
                af[mb][1] = __float_as_uint(As[s][m0+lq+8][kk+lj  ]);
                af[mb][2] = __float_as_uint(As[s][m0+lq  ][kk+lj+4]);
                af[mb][3] = __float_as_uint(As[s][m0+lq+8][kk+lj+4]);
            }
            #pragma unroll
            for (int nb = 0; nb < 4; nb++) {
                const int nc = wn*32 + nb*8 + lq;
                unsigned bb0 = __float_as_uint(Ws[s][nc][kk+lj  ]);
                unsigned bb1 = __float_as_uint(Ws[s][nc][kk+lj+4]);
                #pragma unroll
                for (int mb = 0; mb < 4; mb++)
                    mma_tf32(acc[mb][nb], af[mb], bb0, bb1);
            }
        }
    }

    #pragma unroll
    for (int mb = 0; mb < 4; mb++) {
        const int gi = bm + wm*64 + mb*16 + lq;
        const int bb = gi >> 11, ss = gi & 2047;
        #pragma unroll
        for (int nb = 0; nb < 4; nb++) {
            const int gjl = bn + wn*32 + nb*8 + 2*lj;
            const float bv0 = bias[gjl], bv1 = bias[gjl+1];
            float2 r0, r1;
            r0.x = acc[mb][nb][0] + bv0; r0.y = acc[mb][nb][1] + bv1;
            r1.x = acc[mb][nb][2] + bv0; r1.y = acc[mb][nb][3] + bv1;
            if (mode == 0) {
                *(float2*)(Cout + (size_t)gi * D_MODEL + gjl)     = r0;
                *(float2*)(Cout + (size_t)(gi+8) * D_MODEL + gjl) = r1;
            } else {
                r0.x = __uint_as_float(f2tf(r0.x));
                r0.y = __uint_as_float(f2tf(r0.y));
                r1.x = __uint_as_float(f2tf(r1.x));
                r1.y = __uint_as_float(f2tf(r1.y));
                const int h = gjl >> 6, d = gjl & 63;
                if (mat == 2) {
                    float* p = Cout + (((size_t)bb*NHEAD + h)*DH + d)*SEQ + ss;
                    p[0]       = r0.x;
                    p[SEQ]     = r0.y;
                    p[8]       = r1.x;
                    p[SEQ + 8] = r1.y;
                } else {
                    float* p = Cout + (((size_t)bb*NHEAD + h)*SEQ)*DH + d;
                    *(float2*)(p + (size_t)ss*DH)     = r0;
                    *(float2*)(p + (size_t)(ss+8)*DH) = r1;
                }
            }
        }
    }
}

// ---------------------------------------------------------------------------
// Flash attention, TF32 mma, no-max softmax, 256 thr = 128 queries, warp
// tile 16 rows, 2 blocks/SM. Contraction-slot reindex (slot lj <-> k 2lj)
// => S C-fragment IS the PV A-fragment after exp (register permutation
// {c0,c2,c1,c3}); no P smem round-trip, no syncwarp. Q pre-scaled by
// temp/8*log2e so softmax is a bare ex2.approx.
// ---------------------------------------------------------------------------
#define KT 32
#define NT (SEQ/KT)
#define KST 72
#define VTS 40
#define SM_KS   0
#define SM_VT   (SM_KS + 2*KT*KST*4)              /* 18432 */
#define SM_MS   (SM_VT + 2*DH*VTS*4)              /* +20480 = 38912 */
#define SM_ATTN (SM_MS + SEQ*4)                   /* +8192  = 47104 */

__global__ __launch_bounds__(256, 2) void attn_tc(
    const float* __restrict__ Q, const float* __restrict__ K,
    const float* __restrict__ Vt_g, const int* __restrict__ mask,
    const float* __restrict__ temp, float* __restrict__ O)
{
    extern __shared__ __align__(16) char sm[];
    float (*Ks)[KT][KST] = (float(*)[KT][KST])(sm + SM_KS);
    float (*Vt)[DH][VTS] = (float(*)[DH][VTS])(sm + SM_VT);
    int*  mS             = (int*)             (sm + SM_MS);

    const int bh = blockIdx.y;
    const int b  = bh / NHEAD, h = bh % NHEAD;
    const int q0 = blockIdx.x * 128;
    const float scale = temp[h] * 0.125f * 1.44269504f;  // log2e folded in
    const size_t base  = (size_t)bh * SEQ * DH;   // Q,K layout [S,64]
    const size_t baseV = (size_t)bh * DH * SEQ;   // V layout [64,S]

    const int t    = threadIdx.x;
    const int warp = t >> 5;
    const int lane = t & 31;
    const int lq   = lane >> 2;
    const int lj   = lane & 3;

    const int skey = t >> 3;          // 0..31
    const int sd0  = (t & 7) * 8;     // 0,8,...,56
    const int vd   = t >> 2;          // 0..63
    const int vk0  = (t & 3) * 8;     // 0,8,16,24

    // prologue: stage tile 0 + preload mask row
    {
        const float* kp = K    + base  + (size_t)skey*DH + sd0;
        const float* vp = Vt_g + baseV + (size_t)vd*SEQ  + vk0;
        cp16(&Ks[0][skey][sd0    ], kp);
        cp16(&Ks[0][skey][sd0 + 4], kp + 4);
        cp16(&Vt[0][vd][vk0    ], vp);
        cp16(&Vt[0][vd][vk0 + 4], vp + 4);
        cp_commit();
        #pragma unroll
        for (int i = 0; i < SEQ/256; i++) mS[i*256 + t] = mask[b*SEQ + i*256 + t];
    }

    // Q in A fragments, slot-reindexed (slot lj = d 2lj, slot lj+4 = d 2lj+1)
    unsigned qa[8][4];
    {
        const float* qp0 = Q + base + (size_t)(q0 + warp*16 + lq) * DH;
        const float* qp1 = qp0 + 8 * DH;
        #pragma unroll
        for (int ks = 0; ks < 8; ks++) {
            const int c0 = ks*8 + 2*lj;
            qa[ks][0] = f2tf(qp0[c0]   * scale);
            qa[ks][1] = f2tf(qp1[c0]   * scale);
            qa[ks][2] = f2tf(qp0[c0+1] * scale);
            qa[ks][3] = f2tf(qp1[c0+1] * scale);
        }
    }

    float ls0 = 0.f, ls1 = 0.f;
    float o[8][4];
    #pragma unroll
    for (int nb = 0; nb < 8; nb++)
        #pragma unroll
        for (int c = 0; c < 4; c++) o[nb][c] = 0.f;

    for (int kt = 0; kt < NT; kt++) {
        cp_wait<0>();
        __syncthreads();

        if (kt + 1 < NT) {
            const int s1 = (kt+1) & 1;
            const int k1 = (kt+1) * KT;
            const float* kp = K    + base  + (size_t)(k1 + skey)*DH + sd0;
            const float* vp = Vt_g + baseV + (size_t)vd*SEQ + k1 + vk0;
            cp16(&Ks[s1][skey][sd0    ], kp);
            cp16(&Ks[s1][skey][sd0 + 4], kp + 4);
            cp16(&Vt[s1][vd][vk0    ], vp);
            cp16(&Vt[s1][vd][vk0 + 4], vp + 4);
            cp_commit();
        }

        const int s  = kt & 1;
        const int k0 = kt * KT;

        // ---- S = (scale*Q) K^T : 16x32 per warp; paired LDS.64 B-frags ----
        float sc[4][4];
        #pragma unroll
        for (int nb = 0; nb < 4; nb++)
            #pragma unroll
            for (int c = 0; c < 4; c++) sc[nb][c] = 0.f;

        #pragma unroll
        for (int nb = 0; nb < 4; nb++) {
            const int ncol = nb*8 + lq;
            #pragma unroll
            for (int ks = 0; ks < 8; ks++) {
                float2 kv = *(const float2*)&Ks[s][ncol][ks*8 + 2*lj];
                mma_tf32(sc[nb], qa[ks],
                         __float_as_uint(kv.x), __float_as_uint(kv.y));
            }
        }

        // ---- p = mask ? 2^s : 0 -> PV A-fragments IN REGISTERS ----
        // S C-frag {c0,c1,c2,c3} permutes to PV A-frag {c0,c2,c1,c3}.
        unsigned pa[4][4];
        #pragma unroll
        for (int nb = 0; nb < 4; nb++) {
            const int col0 = nb*8 + 2*lj;
            const int km0 = mS[k0 + col0], km1 = mS[k0 + col0 + 1];
            float p00 = km0 ? ex2(sc[nb][0]) : 0.f;
            float p01 = km1 ? ex2(sc[nb][1]) : 0.f;
            float p10 = km0 ? ex2(sc[nb][2]) : 0.f;
            float p11 = km1 ? ex2(sc[nb][3]) : 0.f;
            ls0 += p00 + p01;
            ls1 += p10 + p11;
            pa[nb][0] = f2tf(p00);
            pa[nb][1] = f2tf(p10);
            pa[nb][2] = f2tf(p01);
            pa[nb][3] = f2tf(p11);
        }

        // ---- O += P V : A-frags from registers, paired LDS.64 for Vt ----
        #pragma unroll
        for (int ks = 0; ks < 4; ks++) {
            #pragma unroll
            for (int nb = 0; nb < 8; nb++) {
                const int ncol = nb*8 + lq;
                float2 vv = *(const float2*)&Vt[s][ncol][ks*8 + 2*lj];
                mma_tf32(o[nb], pa[ks],
                         __float_as_uint(vv.x), __float_as_uint(vv.y));
            }
        }
    }

    // ---- epilogue: reduce row sums, normalize, write tf32-rounded ----
    ls0 += __shfl_xor_sync(0xffffffffu, ls0, 1);
    ls0 += __shfl_xor_sync(0xffffffffu, ls0, 2);
    ls1 += __shfl_xor_sync(0xffffffffu, ls1, 1);
    ls1 += __shfl_xor_sync(0xffffffffu, ls1, 2);
    const float inv0 = 1.0f / ls0;
    const float inv1 = 1.0f / ls1;
    const int qr = q0 + warp*16 + lq;
    float* op0 = O + ((size_t)b*SEQ + qr    )*D_MODEL + h*DH;
    float* op1 = O + ((size_t)b*SEQ + qr + 8)*D_MODEL + h*DH;
    #pragma unroll
    for (int nb = 0; nb < 8; nb++) {
        const int col = nb*8 + 2*lj;
        float2 r0c, r1c;
        r0c.x = __uint_as_float(f2tf(o[nb][0]*inv0));
        r0c.y = __uint_as_float(f2tf(o[nb][1]*inv0));
        r1c.x = __uint_as_float(f2tf(o[nb][2]*inv1));
        r1c.y = __uint_as_float(f2tf(o[nb][3]*inv1));
        *(float2*)(op0 + col) = r0c;
        *(float2*)(op1 + col) = r1c;
    }
}

// ---------------------------------------------------------------------------
extern "C" void kernel_launch(void* const* d_in, const int* in_sizes, int n_in,
                              void* d_out, int out_size)
{
    (void)in_sizes; (void)n_in; (void)out_size;
    const float* x    = (const float*)d_in[0];
    const int*   mask = (const int*)  d_in[1];
    const float* Wq   = (const float*)d_in[2];
    const float* bq   = (const float*)d_in[3];
    const float* Wk   = (const float*)d_in[4];
    const float* bk   = (const float*)d_in[5];
    const float* Wv   = (const float*)d_in[6];
    const float* bv   = (const float*)d_in[7];
    const float* Wo   = (const float*)d_in[8];
    const float* bo   = (const float*)d_in[9];
    const float* temp = (const float*)d_in[10];

    float *QKVb, *Ab, *xt, *Wt;
    cudaGetSymbolAddress((void**)&QKVb, g_QKV);
    cudaGetSymbolAddress((void**)&Ab,   g_A);
    cudaGetSymbolAddress((void**)&xt,   g_xt);
    cudaGetSymbolAddress((void**)&Wt,   g_Wt);

    static int attr_set = 0;
    if (!attr_set) {
        cudaFuncSetAttribute(attn_tc,
            cudaFuncAttributeMaxDynamicSharedMemorySize, SM_ATTN);
        attr_set = 1;
    }

    cvt_tf32<<<(M_ROWS*D_MODEL/4 + 255)/256, 256>>>(x, xt, M_ROWS*D_MODEL/4);
    cvt_w4<<<dim3((WSZ/4 + 255)/256, 1, 4), 256>>>(Wq, Wk, Wv, Wo, Wt);

    gemm_tc<<<dim3(D_MODEL/128, M_ROWS/128, 3), 256>>>(
        xt, Wt, Wt + WSZ, Wt + 2*WSZ, bq, bk, bv, QKVb, 1);

    attn_tc<<<dim3(SEQ/128, BATCH*NHEAD), 256, SM_ATTN>>>(
        QKVb, QKVb + HSZ, QKVb + 2*(size_t)HSZ, mask, temp, Ab);

    gemm_tc<<<dim3(D_MODEL/128, M_ROWS/128, 1), 256>>>(
        Ab, Wt + 3*WSZ, Wt + 3*WSZ, Wt + 3*WSZ, bo, bo, bo, (float*)d_out, 0);
}